// round 5
// baseline (speedup 1.0000x reference)
#include <cuda_runtime.h>
#include <cuda_fp16.h>
#include <cstdint>
#include <math.h>

#define BATCH 1024
#define TSTEPS 12
#define TAU 0.25f
#define BK 128                 // K halfs per pipeline stage
#define SROW 136               // smem row stride (halfs) = 272B; conflict-free for LDSM
#define STG (128 * SROW * 2)   // bytes per tile per stage = 34816
#define BOFF (2 * STG)         // B tiles start after A's two stages
#define SMEM_DYN (4 * STG)     // 139264

// ---------------- static scratch ----------------
__device__ __align__(256) float  g_U[(size_t)BATCH * TSTEPS * 1024];
__device__ __align__(256) __half g_Xh[(size_t)BATCH * TSTEPS * 1024];
__device__ __align__(256) __half g_ah[TSTEPS][(size_t)BATCH * 1024];   // slot t = a_h_{t-1}
__device__ __align__(256) __half g_apc[2][(size_t)BATCH * 1536];       // [a_p | a_c]
__device__ __align__(256) float  g_psc[2][(size_t)BATCH * 1536];       // [p | c]
__device__ __align__(256) __half g_Wp[(size_t)1536 * 2560];            // combined Bt [n][k]
__device__ __align__(256) __half g_Woh[(size_t)1024 * 1024];           // w_oh^T
__device__ __align__(256) float  g_biaspc[1536];

// ---------------- helpers ----------------
__device__ __forceinline__ uint32_t smem_u32(const void* p) {
    uint32_t a;
    asm("{ .reg .u64 t; cvta.to.shared.u64 t, %1; cvt.u32.u64 %0, t; }" : "=r"(a) : "l"(p));
    return a;
}
#define MBARRIER_INIT(mb, c) \
    asm volatile("mbarrier.init.shared.b64 [%0], %1;" :: "r"((uint32_t)(mb)), "r"((uint32_t)(c)) : "memory")
#define MBARRIER_EXPECT_TX(mb, n) \
    asm volatile("mbarrier.arrive.expect_tx.shared.b64 _, [%0], %1;" :: "r"((uint32_t)(mb)), "r"((uint32_t)(n)) : "memory")
#define FENCE_ASYNC_SHARED() asm volatile("fence.proxy.async.shared::cta;" ::: "memory")

#define BULK_G2S(dst, src, nbytes, mb) \
    asm volatile("cp.async.bulk.shared::cta.global.mbarrier::complete_tx::bytes [%0], [%1], %2, [%3];" \
                 :: "r"((uint32_t)(dst)), "l"(src), "r"((uint32_t)(nbytes)), "r"((uint32_t)(mb)) : "memory")

#define MBARRIER_WAIT_PARITY(mb, par) do {                                        \
    uint32_t _m = (uint32_t)(mb); uint32_t _p = (uint32_t)(par); uint32_t _d;     \
    asm volatile("{\n\t.reg .pred p;\n\t"                                         \
        "mbarrier.try_wait.parity.acquire.cta.shared::cta.b64 p, [%1], %2;\n\t"   \
        "selp.b32 %0, 1, 0, p;\n\t}"                                              \
        : "=r"(_d) : "r"(_m), "r"(_p) : "memory");                                \
    if (!_d) {                                                                    \
        asm volatile("{\n\t.reg .pred P1;\n\t"                                    \
        "WL_%=:\n\t"                                                              \
        "mbarrier.try_wait.parity.acquire.cta.shared::cta.b64 P1, [%0], %1, 0x989680;\n\t" \
        "@P1 bra.uni WD_%=;\n\t"                                                  \
        "bra.uni WL_%=;\n\t"                                                      \
        "WD_%=:\n\t}" :: "r"(_m), "r"(_p) : "memory");                            \
    }                                                                             \
} while (0)

#define LDSM_X4(r0, r1, r2, r3, a) \
    asm volatile("ldmatrix.sync.aligned.m8n8.x4.shared.b16 {%0,%1,%2,%3}, [%4];" \
                 : "=r"(r0), "=r"(r1), "=r"(r2), "=r"(r3) : "r"(a))

__device__ __forceinline__ void mma_f16(float* d, const uint32_t* a, const uint32_t* b) {
    asm volatile(
        "mma.sync.aligned.m16n8k16.row.col.f32.f16.f16.f32 "
        "{%0,%1,%2,%3}, {%4,%5,%6,%7}, {%8,%9}, {%0,%1,%2,%3};"
        : "+f"(d[0]), "+f"(d[1]), "+f"(d[2]), "+f"(d[3])
        : "r"(a[0]), "r"(a[1]), "r"(a[2]), "r"(a[3]), "r"(b[0]), "r"(b[1]));
}

// ---------------- fused prep kernels ----------------
__global__ void prep_misc(const float* __restrict__ inputs,
                          const float* __restrict__ bias_p,
                          const float* __restrict__ bias_c) {
    int i = blockIdx.x * blockDim.x + threadIdx.x;   // up to 1,572,864
    const int n8 = BATCH * TSTEPS * 1024 / 8;
    if (i < n8) {  // fp32 -> fp16 input stream
        float4 a = ((const float4*)inputs)[2 * i];
        float4 b = ((const float4*)inputs)[2 * i + 1];
        __half2 h0 = __floats2half2_rn(a.x, a.y);
        __half2 h1 = __floats2half2_rn(a.z, a.w);
        __half2 h2 = __floats2half2_rn(b.x, b.y);
        __half2 h3 = __floats2half2_rn(b.z, b.w);
        uint4 o;
        o.x = *(uint32_t*)&h0; o.y = *(uint32_t*)&h1;
        o.z = *(uint32_t*)&h2; o.w = *(uint32_t*)&h3;
        ((uint4*)g_Xh)[i] = o;
    }
    if (i < BATCH * 1536) { g_apc[0][i] = __float2half_rn(0.5f); g_psc[0][i] = 0.0f; }
    if (i < BATCH * 1024) g_ah[0][i] = __float2half_rn(0.5f);
    if (i < 1536) g_biaspc[i] = (i < 1024) ? bias_p[i] : bias_c[i - 1024];
    if (i < 512 * 2560 / 8)  // zero c-output rows of g_Wp
        ((uint4*)(g_Wp + (size_t)1024 * 2560))[i] = make_uint4(0, 0, 0, 0);
}

// fused 5-way transpose: fp32 [K][N] -> fp16 dst[N][ldd] at column offset
__global__ void prep_tr(const float* __restrict__ w_oh, const float* __restrict__ w_hp,
                        const float* __restrict__ w_pp, const float* __restrict__ w_pc,
                        const float* __restrict__ w_cp) {
    __shared__ float t[32][33];
    const int z = blockIdx.z;
    const float* src; __half* dst; int K, N, ldd, koff;
    switch (z) {
        case 0: src = w_oh; dst = g_Woh; K = 1024; N = 1024; ldd = 1024; koff = 0;    break;
        case 1: src = w_hp; dst = g_Wp;  K = 1024; N = 1024; ldd = 2560; koff = 0;    break;
        case 2: src = w_pp; dst = g_Wp;  K = 1024; N = 1024; ldd = 2560; koff = 1024; break;
        case 3: src = w_cp; dst = g_Wp;  K =  512; N = 1024; ldd = 2560; koff = 2048; break;
        default: src = w_pc; dst = g_Wp + (size_t)1024 * 2560;
                 K = 1024; N = 512; ldd = 2560; koff = 1024; break;
    }
    int n0 = blockIdx.x * 32, k0 = blockIdx.y * 32;
    if (n0 >= N || k0 >= K) return;
    int tx = threadIdx.x, ty = threadIdx.y;  // 32x8
#pragma unroll
    for (int i = 0; i < 4; ++i)
        t[ty + 8 * i][tx] = src[(size_t)(k0 + ty + 8 * i) * N + n0 + tx];
    __syncthreads();
#pragma unroll
    for (int i = 0; i < 4; ++i)
        dst[(size_t)(n0 + ty + 8 * i) * ldd + koff + k0 + tx] = __float2half_rn(t[tx][ty + 8 * i]);
}

// h-scan
__global__ void hscan_kernel(const float* __restrict__ bias_h) {
    int i = blockIdx.x * blockDim.x + threadIdx.x;
    if (i >= BATCH * 1024) return;
    int b = i >> 10, h = i & 1023;
    float bh = bias_h[h];
    float hh = 0.0f;
    const float* Ub = g_U + (size_t)b * TSTEPS * 1024 + h;
#pragma unroll
    for (int t = 0; t < TSTEPS - 1; ++t) {
        hh = TAU * (Ub[(size_t)t * 1024] + bh) + (1.0f - TAU) * hh;
        g_ah[t + 1][i] = __float2half_rn(1.0f / (1.0f + expf(-hh)));
    }
}

// ---------------- fp16 warp-MMA GEMM, bulk-copy pipelined ----------------
struct GDesc {
    const __half* A0; int lda0;
    const __half* A1; int lda1;
    int kSplit;                    // BK-chunks in segment 0
    int nk;                        // total BK-chunks
    const __half* BT; int ldb;
    int N;
    int grid_n;
    const float* bias;
    const float* prev;
    float* state_out;
    __half* act_out;
    float* extra_out;
    int mode;
};

__global__ __launch_bounds__(256, 1)
void tc_gemm(GDesc d) {
    const int bid = blockIdx.x;
    const int bm = bid / d.grid_n;
    const int bn = bid % d.grid_n;

    extern __shared__ __align__(128) char smem[];
    __shared__ __align__(8) uint64_t s_mbar[2];
    const uint32_t sBase = smem_u32(smem);
    const uint32_t mb[2] = { smem_u32(&s_mbar[0]), smem_u32(&s_mbar[1]) };

    const int tid  = threadIdx.x;
    const int warp = tid >> 5;
    const int lane = tid & 31;
    const int wm = warp >> 2;
    const int wn = warp & 3;
    const int g  = lane >> 2;
    const int tg = lane & 3;

    if (tid == 0) { MBARRIER_INIT(mb[0], 32); MBARRIER_INIT(mb[1], 32); }
    __syncthreads();

    const size_t arow = (size_t)bm * 128;
    const size_t brow = (size_t)bn * 128;
    const int ldb = d.ldb;

    float acc[4][4][4];
#pragma unroll
    for (int i = 0; i < 4; ++i)
#pragma unroll
        for (int j = 0; j < 4; ++j)
#pragma unroll
            for (int k = 0; k < 4; ++k) acc[i][j][k] = 0.0f;

    // warp 0 issues bulk row copies: lane handles rows lane, lane+32, lane+64, lane+96
    auto issue_stage = [&](int kc, int s) {
        if (warp != 0) return;
        const __half* Ab; int lda, kbase;
        if (kc < d.kSplit) { Ab = d.A0; lda = d.lda0; kbase = kc * BK; }
        else               { Ab = d.A1; lda = d.lda1; kbase = (kc - d.kSplit) * BK; }
        const __half* Bb = d.BT + (size_t)kc * BK;
        FENCE_ASYNC_SHARED();
        MBARRIER_EXPECT_TX(mb[s], 2048);   // per-lane: 8 rows x 256B
        const uint32_t aSt = sBase + s * STG;
        const uint32_t bSt = sBase + BOFF + s * STG;
#pragma unroll
        for (int r4 = 0; r4 < 4; ++r4) {
            const int row = lane + 32 * r4;
            BULK_G2S(aSt + (uint32_t)row * (SROW * 2),
                     Ab + (arow + row) * (size_t)lda + kbase, 256, mb[s]);
            BULK_G2S(bSt + (uint32_t)row * (SROW * 2),
                     Bb + (brow + row) * (size_t)ldb, 256, mb[s]);
        }
    };

    // ldmatrix lane bases (same fragment map as validated round-4 kernel)
    const uint32_t aLane =
        (uint32_t)(((wm * 64) + (((lane >> 3) & 1) << 3) + (lane & 7)) * SROW +
                   ((lane >> 4) << 3)) * 2u;
    const uint32_t bLane =
        (uint32_t)(((wn * 32) + (((lane >> 4) & 1) << 3) + (lane & 7)) * SROW +
                   (((lane >> 3) & 1) << 3)) * 2u;

    auto compute_stage = [&](int s) {
        const uint32_t aOff = sBase + s * STG + aLane;
        const uint32_t bOff = sBase + BOFF + s * STG + bLane;
#pragma unroll
        for (int k16 = 0; k16 < BK / 16; ++k16) {
            uint32_t af[4][4], bf[2][4];
#pragma unroll
            for (int mt = 0; mt < 4; ++mt)
                LDSM_X4(af[mt][0], af[mt][1], af[mt][2], af[mt][3],
                        aOff + mt * 16 * SROW * 2 + k16 * 32);
#pragma unroll
            for (int np = 0; np < 2; ++np)
                LDSM_X4(bf[np][0], bf[np][1], bf[np][2], bf[np][3],
                        bOff + np * 16 * SROW * 2 + k16 * 32);
#pragma unroll
            for (int mt = 0; mt < 4; ++mt)
#pragma unroll
                for (int nt = 0; nt < 4; ++nt)
                    mma_f16(acc[mt][nt], af[mt], &bf[nt >> 1][(nt & 1) * 2]);
        }
    };

    int ph[2] = { 0, 0 };
    issue_stage(0, 0);
    const int nk = d.nk;
    for (int kc = 0; kc < nk; ++kc) {
        if (kc + 1 < nk) issue_stage(kc + 1, (kc + 1) & 1);
        const int s = kc & 1;
        MBARRIER_WAIT_PARITY(mb[s], ph[s]);
        ph[s] ^= 1;
        compute_stage(s);
        __syncthreads();   // all warps done reading stage s before it is refilled
    }

    // ---------------- epilogue ----------------
    const int N = d.N;
    const bool isP = (bn * 128) < 1024;
#pragma unroll
    for (int mt = 0; mt < 4; ++mt) {
        const int r0 = bm * 128 + wm * 64 + mt * 16 + g;
#pragma unroll
        for (int nt = 0; nt < 4; ++nt) {
            const int c0 = bn * 128 + wn * 32 + nt * 8 + tg * 2;
            if (d.mode == 0) {
                float* o0 = d.state_out + (size_t)r0 * N + c0;
                float* o1 = o0 + (size_t)8 * N;
                *(float2*)o0 = make_float2(acc[mt][nt][0], acc[mt][nt][1]);
                *(float2*)o1 = make_float2(acc[mt][nt][2], acc[mt][nt][3]);
            } else {
                float2 bv = *(const float2*)(d.bias + c0);
#pragma unroll
                for (int h = 0; h < 2; ++h) {
                    const int r = r0 + 8 * h;
                    const size_t off = (size_t)r * N + c0;
                    float2 pv = *(const float2*)(d.prev + off);
                    float2 v, a;
                    v.x = TAU * (acc[mt][nt][2 * h + 0] + bv.x) + (1.0f - TAU) * pv.x;
                    v.y = TAU * (acc[mt][nt][2 * h + 1] + bv.y) + (1.0f - TAU) * pv.y;
                    a.x = 1.0f / (1.0f + expf(-v.x));
                    a.y = 1.0f / (1.0f + expf(-v.y));
                    *(float2*)(d.state_out + off) = v;
                    *(__half2*)(d.act_out + off) = __floats2half2_rn(a.x, a.y);
                    if (d.extra_out && isP)
                        *(float2*)(d.extra_out + (size_t)r * 1024 + c0) = a;
                }
            }
        }
    }
}

// ---------------- launch ----------------
extern "C" void kernel_launch(void* const* d_in, const int* in_sizes, int n_in,
                              void* d_out, int out_size) {
    const float* inputs = (const float*)d_in[0];
    const float* w_oh   = (const float*)d_in[1];
    const float* w_hp   = (const float*)d_in[2];
    const float* w_pp   = (const float*)d_in[3];
    const float* w_pc   = (const float*)d_in[4];
    const float* w_cp   = (const float*)d_in[5];
    const float* bias_h = (const float*)d_in[6];
    const float* bias_p = (const float*)d_in[7];
    const float* bias_c = (const float*)d_in[8];
    float* out = (float*)d_out;                    // [4, B, 1024]

    float *U, *psc, *biaspc;
    __half *Xh, *ah, *apc, *Wp, *Woh;
    cudaGetSymbolAddress((void**)&U,     g_U);
    cudaGetSymbolAddress((void**)&Xh,    g_Xh);
    cudaGetSymbolAddress((void**)&ah,    g_ah);
    cudaGetSymbolAddress((void**)&apc,   g_apc);
    cudaGetSymbolAddress((void**)&psc,   g_psc);
    cudaGetSymbolAddress((void**)&Wp,    g_Wp);
    cudaGetSymbolAddress((void**)&Woh,   g_Woh);
    cudaGetSymbolAddress((void**)&biaspc, g_biaspc);

    cudaFuncSetAttribute(tc_gemm, cudaFuncAttributeMaxDynamicSharedMemorySize, SMEM_DYN);

    const size_t HSZ = (size_t)BATCH * 1024;
    const size_t PCSZ = (size_t)BATCH * 1536;

    // 0) prep (2 launches)
    prep_misc<<<(BATCH * TSTEPS * 1024 / 8 + 255) / 256, 256>>>(inputs, bias_p, bias_c);
    prep_tr<<<dim3(32, 32, 5), dim3(32, 8)>>>(w_oh, w_hp, w_pp, w_pc, w_cp);

    // 1) batched input GEMM: U = Xh @ w_oh  (M = 12288)
    {
        GDesc du = {};
        du.A0 = Xh; du.lda0 = 1024;
        du.A1 = Xh; du.lda1 = 1024;
        du.kSplit = 1024 / BK; du.nk = 1024 / BK;
        du.BT = Woh; du.ldb = 1024;
        du.N = 1024; du.grid_n = 8;
        du.state_out = U; du.mode = 0;
        tc_gemm<<<(BATCH * TSTEPS / 128) * 8, 256, SMEM_DYN>>>(du);
    }

    // 2) h-scan
    hscan_kernel<<<(BATCH * 1024 + 255) / 256, 256>>>(bias_h);

    // 3) sequential combined [p|c] steps
    for (int t = 0; t < TSTEPS; ++t) {
        const int rd = t & 1;
        const int wr = rd ^ 1;

        GDesc ds = {};
        ds.A0 = ah + (size_t)t * HSZ; ds.lda0 = 1024;
        ds.A1 = apc + (size_t)rd * PCSZ; ds.lda1 = 1536;
        ds.kSplit = 1024 / BK; ds.nk = 2560 / BK;
        ds.BT = Wp; ds.ldb = 2560;
        ds.N = 1536; ds.grid_n = 12;
        ds.bias = biaspc;
        ds.prev = psc + (size_t)rd * PCSZ;
        ds.state_out = psc + (size_t)wr * PCSZ;
        ds.act_out = apc + (size_t)wr * PCSZ;
        ds.extra_out = (t >= TSTEPS - 4) ? out + (size_t)(t - (TSTEPS - 4)) * BATCH * 1024 : nullptr;
        ds.mode = 1;

        tc_gemm<<<8 * 12, 256, SMEM_DYN>>>(ds);
    }
}

// round 6
// speedup vs baseline: 4.0025x; 4.0025x over previous
#include <cuda_runtime.h>
#include <cuda_fp16.h>
#include <cstdint>
#include <math.h>

#define BATCH 1024
#define TSTEPS 12
#define TAU 0.25f
#define BK 64                  // K halfs per pipeline stage
#define SROW 72                // smem row stride in halfs (144B), conflict-free
#define ASTG (128 * SROW * 2)  // A tile stage bytes = 18432

// ---------------- static scratch ----------------
__device__ __align__(256) float  g_U[(size_t)BATCH * TSTEPS * 1024];   // x @ w_oh   [b*12+t][h]
__device__ __align__(256) float  g_V[(size_t)TSTEPS * BATCH * 1024];   // a_h @ w_hp [t][b][n]
__device__ __align__(256) __half g_Xh[(size_t)BATCH * TSTEPS * 1024];
__device__ __align__(256) __half g_ah[TSTEPS][(size_t)BATCH * 1024];   // slot t = a_h_{t-1}
__device__ __align__(256) __half g_apc[2][(size_t)BATCH * 1536];       // [a_p | a_c]
__device__ __align__(256) float  g_psc[2][(size_t)BATCH * 1536];       // [p | c]
__device__ __align__(256) __half g_Ws[(size_t)1536 * 1536];            // step weights [n][k]
__device__ __align__(256) __half g_Whp[(size_t)1024 * 1024];           // w_hp^T
__device__ __align__(256) __half g_Woh[(size_t)1024 * 1024];           // w_oh^T
__device__ __align__(256) float  g_biaspc[1536];

// ---------------- helpers ----------------
__device__ __forceinline__ uint32_t smem_u32(const void* p) {
    uint32_t a;
    asm("{ .reg .u64 t; cvta.to.shared.u64 t, %1; cvt.u32.u64 %0, t; }" : "=r"(a) : "l"(p));
    return a;
}
#define CP_ASYNC16(dst, src) \
    asm volatile("cp.async.cg.shared.global [%0], [%1], 16;" :: "r"(dst), "l"(src))
#define CP_COMMIT() asm volatile("cp.async.commit_group;" ::: "memory")
#define CP_WAIT(n)  asm volatile("cp.async.wait_group %0;" :: "n"(n) : "memory")

#define LDSM_X4(r0, r1, r2, r3, a) \
    asm volatile("ldmatrix.sync.aligned.m8n8.x4.shared.b16 {%0,%1,%2,%3}, [%4];" \
                 : "=r"(r0), "=r"(r1), "=r"(r2), "=r"(r3) : "r"(a))

__device__ __forceinline__ void mma_f16(float* d, const uint32_t* a, const uint32_t* b) {
    asm volatile(
        "mma.sync.aligned.m16n8k16.row.col.f32.f16.f16.f32 "
        "{%0,%1,%2,%3}, {%4,%5,%6,%7}, {%8,%9}, {%0,%1,%2,%3};"
        : "+f"(d[0]), "+f"(d[1]), "+f"(d[2]), "+f"(d[3])
        : "r"(a[0]), "r"(a[1]), "r"(a[2]), "r"(a[3]), "r"(b[0]), "r"(b[1]));
}

// ---------------- prep kernels ----------------
__global__ void prep_misc(const float* __restrict__ inputs,
                          const float* __restrict__ bias_p,
                          const float* __restrict__ bias_c) {
    int i = blockIdx.x * blockDim.x + threadIdx.x;   // up to 1,572,864
    const int n8 = BATCH * TSTEPS * 1024 / 8;
    if (i < n8) {  // fp32 -> fp16 input stream
        float4 a = ((const float4*)inputs)[2 * i];
        float4 b = ((const float4*)inputs)[2 * i + 1];
        __half2 h0 = __floats2half2_rn(a.x, a.y);
        __half2 h1 = __floats2half2_rn(a.z, a.w);
        __half2 h2 = __floats2half2_rn(b.x, b.y);
        __half2 h3 = __floats2half2_rn(b.z, b.w);
        uint4 o;
        o.x = *(uint32_t*)&h0; o.y = *(uint32_t*)&h1;
        o.z = *(uint32_t*)&h2; o.w = *(uint32_t*)&h3;
        ((uint4*)g_Xh)[i] = o;
    }
    if (i < BATCH * 1536) { g_apc[0][i] = __float2half_rn(0.5f); g_psc[0][i] = 0.0f; }
    if (i < BATCH * 1024) g_ah[0][i] = __float2half_rn(0.5f);
    if (i < 1536) g_biaspc[i] = (i < 1024) ? bias_p[i] : bias_c[i - 1024];
    if (i < 512 * 512 / 8) {   // zero g_Ws c-rows, K in [1024,1536)
        int row = 1024 + (i >> 6);
        int col = 1024 + (i & 63) * 8;
        *(uint4*)(g_Ws + (size_t)row * 1536 + col) = make_uint4(0, 0, 0, 0);
    }
}

// fused 5-way transpose: fp32 [K][N] -> fp16 dst[N][ldd] at row/column offset
__global__ void prep_tr(const float* __restrict__ w_oh, const float* __restrict__ w_hp,
                        const float* __restrict__ w_pp, const float* __restrict__ w_pc,
                        const float* __restrict__ w_cp) {
    __shared__ float t[32][33];
    const int z = blockIdx.z;
    const float* src; __half* dst; int K, N, ldd, koff;
    switch (z) {
        case 0: src = w_oh; dst = g_Woh; K = 1024; N = 1024; ldd = 1024; koff = 0;    break;
        case 1: src = w_hp; dst = g_Whp; K = 1024; N = 1024; ldd = 1024; koff = 0;    break;
        case 2: src = w_pp; dst = g_Ws;  K = 1024; N = 1024; ldd = 1536; koff = 0;    break;
        case 3: src = w_cp; dst = g_Ws;  K =  512; N = 1024; ldd = 1536; koff = 1024; break;
        default: src = w_pc; dst = g_Ws + (size_t)1024 * 1536;
                 K = 1024; N = 512; ldd = 1536; koff = 0; break;
    }
    int n0 = blockIdx.x * 32, k0 = blockIdx.y * 32;
    if (n0 >= N || k0 >= K) return;
    int tx = threadIdx.x, ty = threadIdx.y;  // 32x8
#pragma unroll
    for (int i = 0; i < 4; ++i)
        t[ty + 8 * i][tx] = src[(size_t)(k0 + ty + 8 * i) * N + n0 + tx];
    __syncthreads();
#pragma unroll
    for (int i = 0; i < 4; ++i)
        dst[(size_t)(n0 + ty + 8 * i) * ldd + koff + k0 + tx] = __float2half_rn(t[tx][ty + 8 * i]);
}

// h-scan, float4-vectorized: slot t+1 <- sigmoid(h_t)
__global__ void hscan_kernel(const float* __restrict__ bias_h) {
    int i = blockIdx.x * blockDim.x + threadIdx.x;
    if (i >= BATCH * 256) return;
    int b = i >> 8, h4 = (i & 255) << 2;
    float4 bh = *(const float4*)(bias_h + h4);
    float4 hh = make_float4(0.f, 0.f, 0.f, 0.f);
    const float* Ub = g_U + (size_t)b * (TSTEPS * 1024) + h4;
#pragma unroll
    for (int t = 0; t < TSTEPS - 1; ++t) {
        float4 u = *(const float4*)(Ub + t * 1024);
        hh.x = TAU * (u.x + bh.x) + (1.0f - TAU) * hh.x;
        hh.y = TAU * (u.y + bh.y) + (1.0f - TAU) * hh.y;
        hh.z = TAU * (u.z + bh.z) + (1.0f - TAU) * hh.z;
        hh.w = TAU * (u.w + bh.w) + (1.0f - TAU) * hh.w;
        __half2 lo = __floats2half2_rn(1.0f / (1.0f + expf(-hh.x)), 1.0f / (1.0f + expf(-hh.y)));
        __half2 hi = __floats2half2_rn(1.0f / (1.0f + expf(-hh.z)), 1.0f / (1.0f + expf(-hh.w)));
        uint2 o; o.x = *(uint32_t*)&lo; o.y = *(uint32_t*)&hi;
        *(uint2*)(g_ah[t + 1] + (size_t)b * 1024 + h4) = o;
    }
}

// ---------------- fp16 warp-MMA GEMM (BN templated) ----------------
struct GDesc {
    const __half* A; int lda;      // activations row-major [M][K]
    int nk;                        // K / BK
    const __half* BT; int ldb;     // weights [N][K]
    int N;                         // output width / ld of state,prev,act
    int grid_n;
    const float* bias;
    const float* prev;
    const float* V;                // hoisted a_h@w_hp term (p-cols only), ld 1024; nullable
    float* state_out;
    __half* act_out;
    float* extra_out;              // d_out slice (p-cols only); nullable
    int mode;                      // 0 raw store, 1 blend+sigmoid
};

template <int BN>
__global__ __launch_bounds__(256, 2)
void tc_gemm(GDesc d) {
    constexpr int NP = BN / 32;          // 16-col B groups per warp
    constexpr int NT = BN / 16;          // n8 mma tiles per warp
    constexpr int BSTG = BN * SROW * 2;  // B tile stage bytes
    const int bid = blockIdx.x;
    const int bm = bid / d.grid_n;
    const int bn = bid % d.grid_n;

    extern __shared__ __align__(16) char smem[];
    const uint32_t sA = smem_u32(smem);
    const uint32_t sB = sA + 2 * ASTG;

    const int tid  = threadIdx.x;
    const int warp = tid >> 5;
    const int lane = tid & 31;
    const int wm = warp >> 1;            // 0..3  (M)
    const int wn = warp & 1;             // 0..1  (N)
    const int g  = lane >> 2;
    const int tg = lane & 3;

    const size_t arow = (size_t)bm * 128;
    const size_t brow = (size_t)bn * BN;

    float acc[2][NT][4];
#pragma unroll
    for (int i = 0; i < 2; ++i)
#pragma unroll
        for (int j = 0; j < NT; ++j)
#pragma unroll
            for (int k = 0; k < 4; ++k) acc[i][j][k] = 0.0f;

    const int lrow = tid >> 3;           // 0..31
    const int lch  = (tid & 7) << 3;     // half col 0,8..56

    auto load_stage = [&](int kc, int s) {
        const int kbase = kc * BK;
        const __half* Ab = d.A + kbase;
        const __half* Bb = d.BT + kbase;
#pragma unroll
        for (int i = 0; i < 4; ++i) {
            int r = lrow + 32 * i;
            CP_ASYNC16(sA + s * ASTG + (uint32_t)(r * SROW + lch) * 2u,
                       Ab + (arow + r) * (size_t)d.lda + lch);
        }
#pragma unroll
        for (int i = 0; i < BN / 32; ++i) {
            int r = lrow + 32 * i;
            CP_ASYNC16(sB + s * BSTG + (uint32_t)(r * SROW + lch) * 2u,
                       Bb + (brow + r) * (size_t)d.ldb + lch);
        }
        CP_COMMIT();
    };

    const uint32_t aLane =
        (uint32_t)(((wm * 32) + (((lane >> 3) & 1) << 3) + (lane & 7)) * SROW +
                   ((lane >> 4) << 3)) * 2u;
    const uint32_t bLane =
        (uint32_t)(((wn * (BN / 2)) + (((lane >> 4) & 1) << 3) + (lane & 7)) * SROW +
                   (((lane >> 3) & 1) << 3)) * 2u;

    auto compute_stage = [&](int s) {
        const uint32_t aOff = sA + s * ASTG + aLane;
        const uint32_t bOff = sB + s * BSTG + bLane;
#pragma unroll
        for (int k16 = 0; k16 < BK / 16; ++k16) {
            uint32_t af[2][4], bf[NP][4];
#pragma unroll
            for (int mt = 0; mt < 2; ++mt)
                LDSM_X4(af[mt][0], af[mt][1], af[mt][2], af[mt][3],
                        aOff + mt * 16 * SROW * 2 + k16 * 32);
#pragma unroll
            for (int np = 0; np < NP; ++np)
                LDSM_X4(bf[np][0], bf[np][1], bf[np][2], bf[np][3],
                        bOff + np * 16 * SROW * 2 + k16 * 32);
#pragma unroll
            for (int mt = 0; mt < 2; ++mt)
#pragma unroll
                for (int nt = 0; nt < NT; ++nt)
                    mma_f16(acc[mt][nt], af[mt], &bf[nt >> 1][(nt & 1) * 2]);
        }
    };

    load_stage(0, 0);
    const int nk = d.nk;
    for (int kc = 0; kc < nk; ++kc) {
        if (kc + 1 < nk) {
            load_stage(kc + 1, (kc + 1) & 1);
            CP_WAIT(1);
        } else {
            CP_WAIT(0);
        }
        __syncthreads();
        compute_stage(kc & 1);
        __syncthreads();
    }

    // ---------------- epilogue ----------------
    const int N = d.N;
#pragma unroll
    for (int mt = 0; mt < 2; ++mt) {
        const int r0 = bm * 128 + wm * 32 + mt * 16 + g;
#pragma unroll
        for (int nt = 0; nt < NT; ++nt) {
            const int c0 = bn * BN + wn * (BN / 2) + nt * 8 + tg * 2;
            if (d.mode == 0) {
                float* o0 = d.state_out + (size_t)r0 * N + c0;
                float* o1 = o0 + (size_t)8 * N;
                *(float2*)o0 = make_float2(acc[mt][nt][0], acc[mt][nt][1]);
                *(float2*)o1 = make_float2(acc[mt][nt][2], acc[mt][nt][3]);
            } else {
                const bool isP = c0 < 1024;
                float2 bv = *(const float2*)(d.bias + c0);
#pragma unroll
                for (int h = 0; h < 2; ++h) {
                    const int r = r0 + 8 * h;
                    const size_t off = (size_t)r * N + c0;
                    float2 pv = *(const float2*)(d.prev + off);
                    float2 vv = make_float2(0.f, 0.f);
                    if (isP) vv = *(const float2*)(d.V + (size_t)r * 1024 + c0);
                    float2 v, a;
                    v.x = TAU * (acc[mt][nt][2 * h + 0] + vv.x + bv.x) + (1.0f - TAU) * pv.x;
                    v.y = TAU * (acc[mt][nt][2 * h + 1] + vv.y + bv.y) + (1.0f - TAU) * pv.y;
                    a.x = 1.0f / (1.0f + expf(-v.x));
                    a.y = 1.0f / (1.0f + expf(-v.y));
                    *(float2*)(d.state_out + off) = v;
                    *(__half2*)(d.act_out + off) = __floats2half2_rn(a.x, a.y);
                    if (d.extra_out && isP)
                        *(float2*)(d.extra_out + (size_t)r * 1024 + c0) = a;
                }
            }
        }
    }
}

// ---------------- launch ----------------
extern "C" void kernel_launch(void* const* d_in, const int* in_sizes, int n_in,
                              void* d_out, int out_size) {
    const float* inputs = (const float*)d_in[0];
    const float* w_oh   = (const float*)d_in[1];
    const float* w_hp   = (const float*)d_in[2];
    const float* w_pp   = (const float*)d_in[3];
    const float* w_pc   = (const float*)d_in[4];
    const float* w_cp   = (const float*)d_in[5];
    const float* bias_h = (const float*)d_in[6];
    const float* bias_p = (const float*)d_in[7];
    const float* bias_c = (const float*)d_in[8];
    float* out = (float*)d_out;                    // [4, B, 1024]

    float *U, *V, *psc, *biaspc;
    __half *Xh, *ah, *apc, *Ws, *Whp, *Woh;
    cudaGetSymbolAddress((void**)&U,     g_U);
    cudaGetSymbolAddress((void**)&V,     g_V);
    cudaGetSymbolAddress((void**)&Xh,    g_Xh);
    cudaGetSymbolAddress((void**)&ah,    g_ah);
    cudaGetSymbolAddress((void**)&apc,   g_apc);
    cudaGetSymbolAddress((void**)&psc,   g_psc);
    cudaGetSymbolAddress((void**)&Ws,    g_Ws);
    cudaGetSymbolAddress((void**)&Whp,   g_Whp);
    cudaGetSymbolAddress((void**)&Woh,   g_Woh);
    cudaGetSymbolAddress((void**)&biaspc, g_biaspc);

    const int SMEM128 = 2 * ASTG + 2 * (128 * SROW * 2);   // 73728
    const int SMEM96  = 2 * ASTG + 2 * (96 * SROW * 2);    // 64512
    cudaFuncSetAttribute(tc_gemm<128>, cudaFuncAttributeMaxDynamicSharedMemorySize, SMEM128);
    cudaFuncSetAttribute(tc_gemm<96>,  cudaFuncAttributeMaxDynamicSharedMemorySize, SMEM96);

    const size_t PCSZ = (size_t)BATCH * 1536;

    // 0) prep
    prep_misc<<<(BATCH * TSTEPS * 1024 / 8 + 255) / 256, 256>>>(inputs, bias_p, bias_c);
    prep_tr<<<dim3(32, 32, 5), dim3(32, 8)>>>(w_oh, w_hp, w_pp, w_pc, w_cp);

    // 1) batched input GEMM: U = Xh @ w_oh  (rows b*12+t)
    {
        GDesc du = {};
        du.A = Xh; du.lda = 1024; du.nk = 1024 / BK;
        du.BT = Woh; du.ldb = 1024;
        du.N = 1024; du.grid_n = 8;
        du.state_out = U; du.mode = 0;
        tc_gemm<128><<<(BATCH * TSTEPS / 128) * 8, 256, SMEM128>>>(du);
    }

    // 2) h-scan -> a_h slots 1..11
    hscan_kernel<<<(BATCH * 256 + 255) / 256, 256>>>(bias_h);

    // 3) hoisted V GEMM: V[t][b][:] = a_h slot t @ w_hp  (rows t*1024+b)
    {
        GDesc dv = {};
        dv.A = ah; dv.lda = 1024; dv.nk = 1024 / BK;
        dv.BT = Whp; dv.ldb = 1024;
        dv.N = 1024; dv.grid_n = 8;
        dv.state_out = V; dv.mode = 0;
        tc_gemm<128><<<(BATCH * TSTEPS / 128) * 8, 256, SMEM128>>>(dv);
    }

    // 4) sequential combined [p|c] steps, K=1536
    for (int t = 0; t < TSTEPS; ++t) {
        const int rd = t & 1;
        const int wr = rd ^ 1;

        GDesc ds = {};
        ds.A = apc + (size_t)rd * PCSZ; ds.lda = 1536; ds.nk = 1536 / BK;
        ds.BT = Ws; ds.ldb = 1536;
        ds.N = 1536; ds.grid_n = 16;
        ds.bias = biaspc;
        ds.prev = psc + (size_t)rd * PCSZ;
        ds.V = V + (size_t)t * BATCH * 1024;
        ds.state_out = psc + (size_t)wr * PCSZ;
        ds.act_out = apc + (size_t)wr * PCSZ;
        ds.extra_out = (t >= TSTEPS - 4) ? out + (size_t)(t - (TSTEPS - 4)) * BATCH * 1024 : nullptr;
        ds.mode = 1;

        tc_gemm<96><<<8 * 16, 256, SMEM96>>>(ds);   // 128 CTAs, one wave
    }
}